// round 2
// baseline (speedup 1.0000x reference)
#include <cuda_runtime.h>
#include <math.h>

#define N_NODES 100000
#define N_EDGES 1600000
#define N_GRAPHS 256
#define D 128
#define EMB (N_NODES * D)          // 12,800,000 floats per embedding layer

// ---------------- scratch (device globals: no allocation) ----------------
__device__ float g_agg[EMB];
__device__ float g_tmp[EMB];

// ---------------- output layout (flattened tuple) ----------------
// embeds   [5][100000][128] @ 0
// pooled   [256][128]       @ 64,000,000
// lin1     [256][128]       @ 64,032,768
// lin1drop [256][128]       @ 64,065,536
// lin2     [256][8]         @ 64,098,304
// soft     [256][8]         @ 64,100,352
#define OFF_POOLED 64000000
#define OFF_LIN1   64032768
#define OFF_LIN1D  64065536
#define OFF_LIN2   64098304
#define OFF_SOFT   64100352

// src selector for GEMM A operand / destinations (avoids host-side symbol address)
#define BUF_EXT 0   // use external pointer
#define BUF_AGG 1   // g_agg
#define BUF_TMP 2   // g_tmp

// ================= GEMM: C[i][j] = sum_k A[i][k] * W[j][k] + b[j] =================
// K = 128 fixed, 128 output cols fixed. Block tile 128x128, thread tile 8x8
// (split 4+4 halves for conflict-free LDS.128), BK=16 double-buffered.
__global__ __launch_bounds__(256, 2)
void gemm128(const float* __restrict__ Aext, int aSel,
             const float* __restrict__ W,
             const float* __restrict__ bias,
             float* __restrict__ Cext, int cSel,
             int N, int doRelu)
{
    const float* A = (aSel == BUF_AGG) ? g_agg : (aSel == BUF_TMP) ? g_tmp : Aext;
    float*       C = (cSel == BUF_AGG) ? g_agg : (cSel == BUF_TMP) ? g_tmp : Cext;

    __shared__ __align__(16) float As[2][16][132];
    __shared__ __align__(16) float Ws[2][16][132];

    const int tid  = threadIdx.x;
    const int row0 = blockIdx.x * 128;
    const int q    = tid & 3;     // k-quad within chunk (0..3)
    const int ld   = tid >> 2;    // 0..63: row/col index for loading
    const int ci   = tid & 15;    // 0..15 col group
    const int ri   = tid >> 4;    // 0..15 row group

    float acc[8][8];
#pragma unroll
    for (int r = 0; r < 8; r++)
#pragma unroll
        for (int c = 0; c < 8; c++) acc[r][c] = 0.0f;

    float4 ra0, ra1, rw0, rw1;

    // ---- load chunk kc into registers ----
    auto ldg_chunk = [&](int kc) {
        const int k = kc * 16 + q * 4;
        const int r0 = row0 + ld, r1 = row0 + ld + 64;
        ra0 = (r0 < N) ? *(const float4*)(A + (size_t)r0 * D + k) : make_float4(0.f, 0.f, 0.f, 0.f);
        ra1 = (r1 < N) ? *(const float4*)(A + (size_t)r1 * D + k) : make_float4(0.f, 0.f, 0.f, 0.f);
        rw0 = *(const float4*)(W + (size_t)ld * D + k);
        rw1 = *(const float4*)(W + (size_t)(ld + 64) * D + k);
    };
    // ---- store registers into smem buffer (transposed) ----
    auto sts_chunk = [&](int buf) {
        const int kk = q * 4;
        As[buf][kk + 0][ld] = ra0.x; As[buf][kk + 1][ld] = ra0.y;
        As[buf][kk + 2][ld] = ra0.z; As[buf][kk + 3][ld] = ra0.w;
        As[buf][kk + 0][ld + 64] = ra1.x; As[buf][kk + 1][ld + 64] = ra1.y;
        As[buf][kk + 2][ld + 64] = ra1.z; As[buf][kk + 3][ld + 64] = ra1.w;
        Ws[buf][kk + 0][ld] = rw0.x; Ws[buf][kk + 1][ld] = rw0.y;
        Ws[buf][kk + 2][ld] = rw0.z; Ws[buf][kk + 3][ld] = rw0.w;
        Ws[buf][kk + 0][ld + 64] = rw1.x; Ws[buf][kk + 1][ld + 64] = rw1.y;
        Ws[buf][kk + 2][ld + 64] = rw1.z; Ws[buf][kk + 3][ld + 64] = rw1.w;
    };

    ldg_chunk(0);
    sts_chunk(0);
    __syncthreads();

    for (int kc = 0; kc < 8; kc++) {
        const int buf = kc & 1;
        if (kc < 7) ldg_chunk(kc + 1);
#pragma unroll
        for (int kk = 0; kk < 16; kk++) {
            float4 a0 = *(const float4*)&As[buf][kk][ri * 4];
            float4 a1 = *(const float4*)&As[buf][kk][64 + ri * 4];
            float4 w0 = *(const float4*)&Ws[buf][kk][ci * 4];
            float4 w1 = *(const float4*)&Ws[buf][kk][64 + ci * 4];
            float a[8] = {a0.x, a0.y, a0.z, a0.w, a1.x, a1.y, a1.z, a1.w};
            float w[8] = {w0.x, w0.y, w0.z, w0.w, w1.x, w1.y, w1.z, w1.w};
#pragma unroll
            for (int r = 0; r < 8; r++)
#pragma unroll
                for (int c = 0; c < 8; c++)
                    acc[r][c] = fmaf(a[r], w[c], acc[r][c]);
        }
        if (kc < 7) {
            sts_chunk(buf ^ 1);
            __syncthreads();
        }
    }

    // epilogue
    float bv[8];
#pragma unroll
    for (int hc = 0; hc < 2; hc++)
#pragma unroll
        for (int c = 0; c < 4; c++)
            bv[hc * 4 + c] = __ldg(bias + hc * 64 + ci * 4 + c);

#pragma unroll
    for (int hr = 0; hr < 2; hr++) {
#pragma unroll
        for (int r = 0; r < 4; r++) {
            const int row = row0 + hr * 64 + ri * 4 + r;
            if (row < N) {
#pragma unroll
                for (int hc = 0; hc < 2; hc++) {
                    const int col = hc * 64 + ci * 4;
                    float4 o;
                    o.x = acc[hr * 4 + r][hc * 4 + 0] + bv[hc * 4 + 0];
                    o.y = acc[hr * 4 + r][hc * 4 + 1] + bv[hc * 4 + 1];
                    o.z = acc[hr * 4 + r][hc * 4 + 2] + bv[hc * 4 + 2];
                    o.w = acc[hr * 4 + r][hc * 4 + 3] + bv[hc * 4 + 3];
                    if (doRelu) {
                        o.x = fmaxf(o.x, 0.f); o.y = fmaxf(o.y, 0.f);
                        o.z = fmaxf(o.z, 0.f); o.w = fmaxf(o.w, 0.f);
                    }
                    *(float4*)(C + (size_t)row * D + col) = o;
                }
            }
        }
    }
}

// ================= agg init: g_agg = (1+eps[l]) * h =================
__global__ void init_agg_k(const float* __restrict__ h,
                           const float* __restrict__ eps, int l)
{
    int i = blockIdx.x * blockDim.x + threadIdx.x;
    if (i < EMB / 4) {
        float e = 1.0f + __ldg(eps + l);
        float4 v = ((const float4*)h)[i];
        v.x *= e; v.y *= e; v.z *= e; v.w *= e;
        ((float4*)g_agg)[i] = v;
    }
}

// ================= edge scatter: g_agg[dst] += mask * h[src] =================
// one thread per (edge, 4-float chunk): 1.6M * 32 = 51.2M threads
__global__ void scatter_k(const float* __restrict__ h,
                          const int* __restrict__ ei, const float* __restrict__ mask)
{
    int t = blockIdx.x * blockDim.x + threadIdx.x;
    if (t >= N_EDGES * 32) return;
    const int e = t >> 5;
    const int c = (t & 31) << 2;
    const int dst = __ldg(ei + e);
    const int src = __ldg(ei + N_EDGES + e);
    const float m = __ldg(mask + e);
    float4 v = *(const float4*)(h + (size_t)src * D + c);
    float* p = g_agg + (size_t)dst * D + c;
    atomicAdd(p + 0, v.x * m);
    atomicAdd(p + 1, v.y * m);
    atomicAdd(p + 2, v.z * m);
    atomicAdd(p + 3, v.w * m);
}

// ================= per-graph pooling over all 5 embeddings =================
__device__ __forceinline__ int lower_bound_i(const int* a, int n, int v)
{
    int lo = 0, hi = n;
    while (lo < hi) {
        int mid = (lo + hi) >> 1;
        if (a[mid] < v) lo = mid + 1; else hi = mid;
    }
    return lo;
}

__global__ void pool_k(const float* __restrict__ embeds, const int* __restrict__ batch,
                       float* __restrict__ pooled)
{
    const int g = blockIdx.x;
    const int j = threadIdx.x; // 128 threads = feature dim
    __shared__ int sse[2];
    if (j == 0) sse[0] = lower_bound_i(batch, N_NODES, g);
    if (j == 1) sse[1] = lower_bound_i(batch, N_NODES, g + 1);
    __syncthreads();
    const int s = sse[0], epos = sse[1];
    float acc = 0.0f;
    for (int n = s; n < epos; n++) {
        const float* p = embeds + (size_t)n * D + j;
        acc += p[0] + p[EMB] + p[2 * (size_t)EMB] + p[3 * (size_t)EMB] + p[4 * (size_t)EMB];
    }
    pooled[g * D + j] = acc;
}

// ================= head: lin1(relu) -> lin2 -> softmax =================
__global__ void head_k(const float* __restrict__ pooled,
                       const float* __restrict__ W1, const float* __restrict__ b1,
                       const float* __restrict__ W2, const float* __restrict__ b2,
                       float* __restrict__ lin1, float* __restrict__ lin1d,
                       float* __restrict__ lin2, float* __restrict__ soft)
{
    const int g = blockIdx.x;
    const int j = threadIdx.x; // 128 threads
    __shared__ float ps[D];
    __shared__ float l1[D];
    __shared__ float lo[8];

    ps[j] = pooled[g * D + j];
    __syncthreads();

    float acc = __ldg(b1 + j);
    const float4* wr = (const float4*)(W1 + (size_t)j * D);
#pragma unroll 8
    for (int k4 = 0; k4 < 32; k4++) {
        float4 w = __ldg(wr + k4);
        acc = fmaf(ps[k4 * 4 + 0], w.x, acc);
        acc = fmaf(ps[k4 * 4 + 1], w.y, acc);
        acc = fmaf(ps[k4 * 4 + 2], w.z, acc);
        acc = fmaf(ps[k4 * 4 + 3], w.w, acc);
    }
    acc = fmaxf(acc, 0.0f);
    lin1[g * D + j] = acc;
    lin1d[g * D + j] = acc;
    l1[j] = acc;
    __syncthreads();

    if (j < 8) {
        float a2 = __ldg(b2 + j);
        const float4* w2r = (const float4*)(W2 + (size_t)j * D);
#pragma unroll 8
        for (int k4 = 0; k4 < 32; k4++) {
            float4 w = __ldg(w2r + k4);
            a2 = fmaf(l1[k4 * 4 + 0], w.x, a2);
            a2 = fmaf(l1[k4 * 4 + 1], w.y, a2);
            a2 = fmaf(l1[k4 * 4 + 2], w.z, a2);
            a2 = fmaf(l1[k4 * 4 + 3], w.w, a2);
        }
        lin2[g * 8 + j] = a2;
        lo[j] = a2;
    }
    __syncthreads();
    if (j < 8) {
        float m = lo[0];
#pragma unroll
        for (int t = 1; t < 8; t++) m = fmaxf(m, lo[t]);
        float s = 0.0f;
#pragma unroll
        for (int t = 0; t < 8; t++) s += expf(lo[t] - m);
        soft[g * 8 + j] = expf(lo[j] - m) / s;
    }
}

// ================= launch =================
extern "C" void kernel_launch(void* const* d_in, const int* in_sizes, int n_in,
                              void* d_out, int out_size)
{
    const float* x       = (const float*)d_in[0];
    const int*   ei      = (const int*)  d_in[1];
    const float* emask   = (const float*)d_in[2];
    const int*   batch   = (const int*)  d_in[3];
    const float* eps     = (const float*)d_in[4];
    const float* W_first = (const float*)d_in[5];
    const float* b_first = (const float*)d_in[6];
    const float* gin_W   = (const float*)d_in[7];
    const float* gin_b   = (const float*)d_in[8];
    const float* W1      = (const float*)d_in[9];
    const float* b1      = (const float*)d_in[10];
    const float* W2      = (const float*)d_in[11];
    const float* b2      = (const float*)d_in[12];
    float* out = (float*)d_out;

    const dim3 gB((N_NODES + 127) / 128);

    // embeds[0] = x @ W_first^T + b_first (no relu)
    gemm128<<<gB, 256>>>(x, BUF_EXT, W_first, b_first, out, BUF_EXT, N_NODES, 0);

    for (int l = 0; l < 4; l++) {
        const float* h = out + (size_t)l * EMB;
        init_agg_k<<<(EMB / 4 + 255) / 256, 256>>>(h, eps, l);
        scatter_k<<<(N_EDGES * 32) / 256, 256>>>(h, ei, emask);
        gemm128<<<gB, 256>>>(nullptr, BUF_AGG, gin_W + (size_t)(2 * l) * D * D,
                             gin_b + (2 * l) * D, nullptr, BUF_TMP, N_NODES, 1);
        gemm128<<<gB, 256>>>(nullptr, BUF_TMP, gin_W + (size_t)(2 * l + 1) * D * D,
                             gin_b + (2 * l + 1) * D, out + (size_t)(l + 1) * EMB,
                             BUF_EXT, N_NODES, 1);
    }

    pool_k<<<N_GRAPHS, 128>>>(out, batch, out + OFF_POOLED);
    head_k<<<N_GRAPHS, 128>>>(out + OFF_POOLED, W1, b1, W2, b2,
                              out + OFF_LIN1, out + OFF_LIN1D,
                              out + OFF_LIN2, out + OFF_SOFT);
}

// round 3
// speedup vs baseline: 1.3510x; 1.3510x over previous
#include <cuda_runtime.h>
#include <math.h>

#define N_NODES 100000
#define N_EDGES 1600000
#define N_GRAPHS 256
#define D 128
#define EMB (N_NODES * D)

// ---------------- scratch (device globals: no allocation) ----------------
__device__ float g_agg[EMB];
__device__ float g_tmp[EMB];
__device__ int2  g_edge[N_EDGES];     // packed {src, mask bits} sorted by dst
__device__ int   g_row[N_NODES + 1];  // CSR row starts
__device__ int   g_cur[N_NODES];      // fill cursors
__device__ int   g_cnt[N_NODES];      // histogram

// ---------------- output layout (flattened tuple) ----------------
#define OFF_POOLED 64000000
#define OFF_LIN1   64032768
#define OFF_LIN1D  64065536
#define OFF_LIN2   64098304
#define OFF_SOFT   64100352

#define BUF_EXT 0
#define BUF_AGG 1
#define BUF_TMP 2

// ================= GEMM: C[i][j] = sum_k A[i][k] * W[j][k] + b[j] =================
__global__ __launch_bounds__(256, 2)
void gemm128(const float* __restrict__ Aext, int aSel,
             const float* __restrict__ W,
             const float* __restrict__ bias,
             float* __restrict__ Cext, int cSel,
             int N, int doRelu)
{
    const float* A = (aSel == BUF_AGG) ? g_agg : (aSel == BUF_TMP) ? g_tmp : Aext;
    float*       C = (cSel == BUF_AGG) ? g_agg : (cSel == BUF_TMP) ? g_tmp : Cext;

    __shared__ __align__(16) float As[2][16][132];
    __shared__ __align__(16) float Ws[2][16][132];

    const int tid  = threadIdx.x;
    const int row0 = blockIdx.x * 128;
    const int q    = tid & 3;
    const int ld   = tid >> 2;
    const int ci   = tid & 15;
    const int ri   = tid >> 4;

    float acc[8][8];
#pragma unroll
    for (int r = 0; r < 8; r++)
#pragma unroll
        for (int c = 0; c < 8; c++) acc[r][c] = 0.0f;

    float4 ra0, ra1, rw0, rw1;

    auto ldg_chunk = [&](int kc) {
        const int k = kc * 16 + q * 4;
        const int r0 = row0 + ld, r1 = row0 + ld + 64;
        ra0 = (r0 < N) ? *(const float4*)(A + (size_t)r0 * D + k) : make_float4(0.f, 0.f, 0.f, 0.f);
        ra1 = (r1 < N) ? *(const float4*)(A + (size_t)r1 * D + k) : make_float4(0.f, 0.f, 0.f, 0.f);
        rw0 = *(const float4*)(W + (size_t)ld * D + k);
        rw1 = *(const float4*)(W + (size_t)(ld + 64) * D + k);
    };
    auto sts_chunk = [&](int buf) {
        const int kk = q * 4;
        As[buf][kk + 0][ld] = ra0.x; As[buf][kk + 1][ld] = ra0.y;
        As[buf][kk + 2][ld] = ra0.z; As[buf][kk + 3][ld] = ra0.w;
        As[buf][kk + 0][ld + 64] = ra1.x; As[buf][kk + 1][ld + 64] = ra1.y;
        As[buf][kk + 2][ld + 64] = ra1.z; As[buf][kk + 3][ld + 64] = ra1.w;
        Ws[buf][kk + 0][ld] = rw0.x; Ws[buf][kk + 1][ld] = rw0.y;
        Ws[buf][kk + 2][ld] = rw0.z; Ws[buf][kk + 3][ld] = rw0.w;
        Ws[buf][kk + 0][ld + 64] = rw1.x; Ws[buf][kk + 1][ld + 64] = rw1.y;
        Ws[buf][kk + 2][ld + 64] = rw1.z; Ws[buf][kk + 3][ld + 64] = rw1.w;
    };

    ldg_chunk(0);
    sts_chunk(0);
    __syncthreads();

    for (int kc = 0; kc < 8; kc++) {
        const int buf = kc & 1;
        if (kc < 7) ldg_chunk(kc + 1);
#pragma unroll
        for (int kk = 0; kk < 16; kk++) {
            float4 a0 = *(const float4*)&As[buf][kk][ri * 4];
            float4 a1 = *(const float4*)&As[buf][kk][64 + ri * 4];
            float4 w0 = *(const float4*)&Ws[buf][kk][ci * 4];
            float4 w1 = *(const float4*)&Ws[buf][kk][64 + ci * 4];
            float a[8] = {a0.x, a0.y, a0.z, a0.w, a1.x, a1.y, a1.z, a1.w};
            float w[8] = {w0.x, w0.y, w0.z, w0.w, w1.x, w1.y, w1.z, w1.w};
#pragma unroll
            for (int r = 0; r < 8; r++)
#pragma unroll
                for (int c = 0; c < 8; c++)
                    acc[r][c] = fmaf(a[r], w[c], acc[r][c]);
        }
        if (kc < 7) {
            sts_chunk(buf ^ 1);
            __syncthreads();
        }
    }

    float bv[8];
#pragma unroll
    for (int hc = 0; hc < 2; hc++)
#pragma unroll
        for (int c = 0; c < 4; c++)
            bv[hc * 4 + c] = __ldg(bias + hc * 64 + ci * 4 + c);

#pragma unroll
    for (int hr = 0; hr < 2; hr++) {
#pragma unroll
        for (int r = 0; r < 4; r++) {
            const int row = row0 + hr * 64 + ri * 4 + r;
            if (row < N) {
#pragma unroll
                for (int hc = 0; hc < 2; hc++) {
                    const int col = hc * 64 + ci * 4;
                    float4 o;
                    o.x = acc[hr * 4 + r][hc * 4 + 0] + bv[hc * 4 + 0];
                    o.y = acc[hr * 4 + r][hc * 4 + 1] + bv[hc * 4 + 1];
                    o.z = acc[hr * 4 + r][hc * 4 + 2] + bv[hc * 4 + 2];
                    o.w = acc[hr * 4 + r][hc * 4 + 3] + bv[hc * 4 + 3];
                    if (doRelu) {
                        o.x = fmaxf(o.x, 0.f); o.y = fmaxf(o.y, 0.f);
                        o.z = fmaxf(o.z, 0.f); o.w = fmaxf(o.w, 0.f);
                    }
                    *(float4*)(C + (size_t)row * D + col) = o;
                }
            }
        }
    }
}

// ================= CSR build =================
__global__ void zero_cnt_k()
{
    int i = blockIdx.x * blockDim.x + threadIdx.x;
    if (i < N_NODES) g_cnt[i] = 0;
}

__global__ void hist_k(const int* __restrict__ ei)
{
    int e = blockIdx.x * blockDim.x + threadIdx.x;
    if (e < N_EDGES) atomicAdd(&g_cnt[__ldg(ei + e)], 1);
}

// single-block exclusive scan of g_cnt -> g_row, g_cur
#define SCAN_T 1024
#define SCAN_CHUNK ((N_NODES + SCAN_T - 1) / SCAN_T)   // 98
__global__ __launch_bounds__(SCAN_T)
void scan_k()
{
    __shared__ int s[SCAN_T];
    const int t = threadIdx.x;
    const int base = t * SCAN_CHUNK;
    int sum = 0;
    for (int i = 0; i < SCAN_CHUNK; i++) {
        int idx = base + i;
        if (idx < N_NODES) sum += g_cnt[idx];
    }
    s[t] = sum;
    __syncthreads();
    // Hillis-Steele inclusive scan
    for (int off = 1; off < SCAN_T; off <<= 1) {
        int v = (t >= off) ? s[t - off] : 0;
        __syncthreads();
        s[t] += v;
        __syncthreads();
    }
    int run = (t == 0) ? 0 : s[t - 1];
    for (int i = 0; i < SCAN_CHUNK; i++) {
        int idx = base + i;
        if (idx < N_NODES) {
            g_row[idx] = run;
            g_cur[idx] = run;
            run += g_cnt[idx];
        }
    }
    if (t == 0) g_row[N_NODES] = s[SCAN_T - 1];
}

__global__ void fill_k(const int* __restrict__ ei, const float* __restrict__ mask)
{
    int e = blockIdx.x * blockDim.x + threadIdx.x;
    if (e >= N_EDGES) return;
    const int dst = __ldg(ei + e);
    const int src = __ldg(ei + N_EDGES + e);
    const float m = __ldg(mask + e);
    int pos = atomicAdd(&g_cur[dst], 1);
    g_edge[pos] = make_int2(src, __float_as_int(m));
}

// ================= fused gather: g_agg[n] = (1+eps)*h[n] + sum m*h[src] ======
// one warp per node, lane handles 4 features
__global__ __launch_bounds__(256)
void gather_k(const float* __restrict__ h, const float* __restrict__ eps, int l)
{
    const int warp = (blockIdx.x * blockDim.x + threadIdx.x) >> 5;
    const int lane = threadIdx.x & 31;
    if (warp >= N_NODES) return;
    const float4* __restrict__ h4 = (const float4*)h;
    const float e1 = 1.0f + __ldg(eps + l);

    float4 v = h4[(size_t)warp * 32 + lane];
    float4 acc = make_float4(v.x * e1, v.y * e1, v.z * e1, v.w * e1);

    int e = g_row[warp];
    const int r1 = g_row[warp + 1];
    // unroll 2 for MLP on the dependent edge->row load chains
    for (; e + 2 <= r1; e += 2) {
        int2 p0 = g_edge[e];
        int2 p1 = g_edge[e + 1];
        float4 v0 = h4[(size_t)p0.x * 32 + lane];
        float4 v1 = h4[(size_t)p1.x * 32 + lane];
        float m0 = __int_as_float(p0.y);
        float m1 = __int_as_float(p1.y);
        acc.x = fmaf(m0, v0.x, acc.x); acc.y = fmaf(m0, v0.y, acc.y);
        acc.z = fmaf(m0, v0.z, acc.z); acc.w = fmaf(m0, v0.w, acc.w);
        acc.x = fmaf(m1, v1.x, acc.x); acc.y = fmaf(m1, v1.y, acc.y);
        acc.z = fmaf(m1, v1.z, acc.z); acc.w = fmaf(m1, v1.w, acc.w);
    }
    if (e < r1) {
        int2 p0 = g_edge[e];
        float4 v0 = h4[(size_t)p0.x * 32 + lane];
        float m0 = __int_as_float(p0.y);
        acc.x = fmaf(m0, v0.x, acc.x); acc.y = fmaf(m0, v0.y, acc.y);
        acc.z = fmaf(m0, v0.z, acc.z); acc.w = fmaf(m0, v0.w, acc.w);
    }
    ((float4*)g_agg)[(size_t)warp * 32 + lane] = acc;
}

// ================= pooling =================
__device__ __forceinline__ int lower_bound_i(const int* a, int n, int v)
{
    int lo = 0, hi = n;
    while (lo < hi) {
        int mid = (lo + hi) >> 1;
        if (a[mid] < v) lo = mid + 1; else hi = mid;
    }
    return lo;
}

__global__ void zero_pool_k(float* __restrict__ pooled)
{
    int i = blockIdx.x * blockDim.x + threadIdx.x;
    if (i < N_GRAPHS * D) pooled[i] = 0.0f;
}

// one block per (graph, layer); accumulate into pooled with atomics
__global__ void pool_part_k(const float* __restrict__ embeds,
                            const int* __restrict__ batch,
                            float* __restrict__ pooled)
{
    const int g = blockIdx.x & (N_GRAPHS - 1);
    const int l = blockIdx.x >> 8;
    const int j = threadIdx.x;
    __shared__ int sse[2];
    if (j == 0) sse[0] = lower_bound_i(batch, N_NODES, g);
    if (j == 1) sse[1] = lower_bound_i(batch, N_NODES, g + 1);
    __syncthreads();
    const int s = sse[0], epos = sse[1];
    const float* __restrict__ base = embeds + (size_t)l * EMB;
    float acc = 0.0f;
    int n = s;
    for (; n + 4 <= epos; n += 4) {
        acc += base[(size_t)(n + 0) * D + j] + base[(size_t)(n + 1) * D + j]
             + base[(size_t)(n + 2) * D + j] + base[(size_t)(n + 3) * D + j];
    }
    for (; n < epos; n++) acc += base[(size_t)n * D + j];
    if (acc != 0.0f || true) atomicAdd(&pooled[g * D + j], acc);
}

// ================= head =================
__global__ void head_k(const float* __restrict__ pooled,
                       const float* __restrict__ W1, const float* __restrict__ b1,
                       const float* __restrict__ W2, const float* __restrict__ b2,
                       float* __restrict__ lin1, float* __restrict__ lin1d,
                       float* __restrict__ lin2, float* __restrict__ soft)
{
    const int g = blockIdx.x;
    const int j = threadIdx.x;
    __shared__ float ps[D];
    __shared__ float l1[D];
    __shared__ float lo[8];

    ps[j] = pooled[g * D + j];
    __syncthreads();

    float acc = __ldg(b1 + j);
    const float4* wr = (const float4*)(W1 + (size_t)j * D);
#pragma unroll 8
    for (int k4 = 0; k4 < 32; k4++) {
        float4 w = __ldg(wr + k4);
        acc = fmaf(ps[k4 * 4 + 0], w.x, acc);
        acc = fmaf(ps[k4 * 4 + 1], w.y, acc);
        acc = fmaf(ps[k4 * 4 + 2], w.z, acc);
        acc = fmaf(ps[k4 * 4 + 3], w.w, acc);
    }
    acc = fmaxf(acc, 0.0f);
    lin1[g * D + j] = acc;
    lin1d[g * D + j] = acc;
    l1[j] = acc;
    __syncthreads();

    if (j < 8) {
        float a2 = __ldg(b2 + j);
        const float4* w2r = (const float4*)(W2 + (size_t)j * D);
#pragma unroll 8
        for (int k4 = 0; k4 < 32; k4++) {
            float4 w = __ldg(w2r + k4);
            a2 = fmaf(l1[k4 * 4 + 0], w.x, a2);
            a2 = fmaf(l1[k4 * 4 + 1], w.y, a2);
            a2 = fmaf(l1[k4 * 4 + 2], w.z, a2);
            a2 = fmaf(l1[k4 * 4 + 3], w.w, a2);
        }
        lin2[g * 8 + j] = a2;
        lo[j] = a2;
    }
    __syncthreads();
    if (j < 8) {
        float m = lo[0];
#pragma unroll
        for (int t = 1; t < 8; t++) m = fmaxf(m, lo[t]);
        float s = 0.0f;
#pragma unroll
        for (int t = 0; t < 8; t++) s += expf(lo[t] - m);
        soft[g * 8 + j] = expf(lo[j] - m) / s;
    }
}

// ================= launch =================
extern "C" void kernel_launch(void* const* d_in, const int* in_sizes, int n_in,
                              void* d_out, int out_size)
{
    const float* x       = (const float*)d_in[0];
    const int*   ei      = (const int*)  d_in[1];
    const float* emask   = (const float*)d_in[2];
    const int*   batch   = (const int*)  d_in[3];
    const float* eps     = (const float*)d_in[4];
    const float* W_first = (const float*)d_in[5];
    const float* b_first = (const float*)d_in[6];
    const float* gin_W   = (const float*)d_in[7];
    const float* gin_b   = (const float*)d_in[8];
    const float* W1      = (const float*)d_in[9];
    const float* b1      = (const float*)d_in[10];
    const float* W2      = (const float*)d_in[11];
    const float* b2      = (const float*)d_in[12];
    float* out = (float*)d_out;

    const dim3 gB((N_NODES + 127) / 128);
    const int eB = (N_EDGES + 255) / 256;

    // ---- CSR build (once per launch; reused by 4 gathers) ----
    zero_cnt_k<<<(N_NODES + 255) / 256, 256>>>();
    hist_k<<<eB, 256>>>(ei);
    scan_k<<<1, SCAN_T>>>();
    fill_k<<<eB, 256>>>(ei, emask);

    // embeds[0] = x @ W_first^T + b_first (no relu)
    gemm128<<<gB, 256>>>(x, BUF_EXT, W_first, b_first, out, BUF_EXT, N_NODES, 0);

    for (int l = 0; l < 4; l++) {
        const float* h = out + (size_t)l * EMB;
        gather_k<<<(N_NODES * 32 + 255) / 256, 256>>>(h, eps, l);
        gemm128<<<gB, 256>>>(nullptr, BUF_AGG, gin_W + (size_t)(2 * l) * D * D,
                             gin_b + (2 * l) * D, nullptr, BUF_TMP, N_NODES, 1);
        gemm128<<<gB, 256>>>(nullptr, BUF_TMP, gin_W + (size_t)(2 * l + 1) * D * D,
                             gin_b + (2 * l + 1) * D, out + (size_t)(l + 1) * EMB,
                             BUF_EXT, N_NODES, 1);
    }

    zero_pool_k<<<(N_GRAPHS * D + 255) / 256, 256>>>(out + OFF_POOLED);
    pool_part_k<<<N_GRAPHS * 5, 128>>>(out, batch, out + OFF_POOLED);
    head_k<<<N_GRAPHS, 128>>>(out + OFF_POOLED, W1, b1, W2, b2,
                              out + OFF_LIN1, out + OFF_LIN1D,
                              out + OFF_LIN2, out + OFF_SOFT);
}

// round 4
// speedup vs baseline: 2.0671x; 1.5300x over previous
#include <cuda_runtime.h>
#include <math.h>

#define N_NODES 100000
#define N_EDGES 1600000
#define N_GRAPHS 256
#define D 128
#define EMB (N_NODES * D)

// ---------------- scratch (device globals: no allocation) ----------------
__device__ float g_agg[EMB];
__device__ float g_tmp[EMB];
__device__ int2  g_edge[N_EDGES];     // packed {src, mask bits} sorted by dst
__device__ int   g_row[N_NODES + 1];  // CSR row starts
__device__ int   g_cur[N_NODES];      // fill cursors
__device__ int   g_cnt[N_NODES];      // histogram

// ---------------- output layout (flattened tuple) ----------------
#define OFF_POOLED 64000000
#define OFF_LIN1   64032768
#define OFF_LIN1D  64065536
#define OFF_LIN2   64098304
#define OFF_SOFT   64100352

#define BUF_EXT 0
#define BUF_AGG 1
#define BUF_TMP 2

// ================= GEMM: C[i][j] = sum_k A[i][k] * W[j][k] + b[j] =================
__global__ __launch_bounds__(256, 2)
void gemm128(const float* __restrict__ Aext, int aSel,
             const float* __restrict__ W,
             const float* __restrict__ bias,
             float* __restrict__ Cext, int cSel,
             int N, int doRelu)
{
    const float* A = (aSel == BUF_AGG) ? g_agg : (aSel == BUF_TMP) ? g_tmp : Aext;
    float*       C = (cSel == BUF_AGG) ? g_agg : (cSel == BUF_TMP) ? g_tmp : Cext;

    __shared__ __align__(16) float As[2][16][132];
    __shared__ __align__(16) float Ws[2][16][132];

    const int tid  = threadIdx.x;
    const int row0 = blockIdx.x * 128;
    const int q    = tid & 3;
    const int ld   = tid >> 2;
    const int ci   = tid & 15;
    const int ri   = tid >> 4;

    float acc[8][8];
#pragma unroll
    for (int r = 0; r < 8; r++)
#pragma unroll
        for (int c = 0; c < 8; c++) acc[r][c] = 0.0f;

    float4 ra0, ra1, rw0, rw1;

    auto ldg_chunk = [&](int kc) {
        const int k = kc * 16 + q * 4;
        const int r0 = row0 + ld, r1 = row0 + ld + 64;
        ra0 = (r0 < N) ? *(const float4*)(A + (size_t)r0 * D + k) : make_float4(0.f, 0.f, 0.f, 0.f);
        ra1 = (r1 < N) ? *(const float4*)(A + (size_t)r1 * D + k) : make_float4(0.f, 0.f, 0.f, 0.f);
        rw0 = *(const float4*)(W + (size_t)ld * D + k);
        rw1 = *(const float4*)(W + (size_t)(ld + 64) * D + k);
    };
    auto sts_chunk = [&](int buf) {
        const int kk = q * 4;
        As[buf][kk + 0][ld] = ra0.x; As[buf][kk + 1][ld] = ra0.y;
        As[buf][kk + 2][ld] = ra0.z; As[buf][kk + 3][ld] = ra0.w;
        As[buf][kk + 0][ld + 64] = ra1.x; As[buf][kk + 1][ld + 64] = ra1.y;
        As[buf][kk + 2][ld + 64] = ra1.z; As[buf][kk + 3][ld + 64] = ra1.w;
        Ws[buf][kk + 0][ld] = rw0.x; Ws[buf][kk + 1][ld] = rw0.y;
        Ws[buf][kk + 2][ld] = rw0.z; Ws[buf][kk + 3][ld] = rw0.w;
        Ws[buf][kk + 0][ld + 64] = rw1.x; Ws[buf][kk + 1][ld + 64] = rw1.y;
        Ws[buf][kk + 2][ld + 64] = rw1.z; Ws[buf][kk + 3][ld + 64] = rw1.w;
    };

    ldg_chunk(0);
    sts_chunk(0);
    __syncthreads();

    for (int kc = 0; kc < 8; kc++) {
        const int buf = kc & 1;
        if (kc < 7) ldg_chunk(kc + 1);
#pragma unroll
        for (int kk = 0; kk < 16; kk++) {
            float4 a0 = *(const float4*)&As[buf][kk][ri * 4];
            float4 a1 = *(const float4*)&As[buf][kk][64 + ri * 4];
            float4 w0 = *(const float4*)&Ws[buf][kk][ci * 4];
            float4 w1 = *(const float4*)&Ws[buf][kk][64 + ci * 4];
            float a[8] = {a0.x, a0.y, a0.z, a0.w, a1.x, a1.y, a1.z, a1.w};
            float w[8] = {w0.x, w0.y, w0.z, w0.w, w1.x, w1.y, w1.z, w1.w};
#pragma unroll
            for (int r = 0; r < 8; r++)
#pragma unroll
                for (int c = 0; c < 8; c++)
                    acc[r][c] = fmaf(a[r], w[c], acc[r][c]);
        }
        if (kc < 7) {
            sts_chunk(buf ^ 1);
            __syncthreads();
        }
    }

    float bv[8];
#pragma unroll
    for (int hc = 0; hc < 2; hc++)
#pragma unroll
        for (int c = 0; c < 4; c++)
            bv[hc * 4 + c] = __ldg(bias + hc * 64 + ci * 4 + c);

#pragma unroll
    for (int hr = 0; hr < 2; hr++) {
#pragma unroll
        for (int r = 0; r < 4; r++) {
            const int row = row0 + hr * 64 + ri * 4 + r;
            if (row < N) {
#pragma unroll
                for (int hc = 0; hc < 2; hc++) {
                    const int col = hc * 64 + ci * 4;
                    float4 o;
                    o.x = acc[hr * 4 + r][hc * 4 + 0] + bv[hc * 4 + 0];
                    o.y = acc[hr * 4 + r][hc * 4 + 1] + bv[hc * 4 + 1];
                    o.z = acc[hr * 4 + r][hc * 4 + 2] + bv[hc * 4 + 2];
                    o.w = acc[hr * 4 + r][hc * 4 + 3] + bv[hc * 4 + 3];
                    if (doRelu) {
                        o.x = fmaxf(o.x, 0.f); o.y = fmaxf(o.y, 0.f);
                        o.z = fmaxf(o.z, 0.f); o.w = fmaxf(o.w, 0.f);
                    }
                    *(float4*)(C + (size_t)row * D + col) = o;
                }
            }
        }
    }
}

// ================= CSR build =================
__global__ void zero_cnt_k()
{
    int i = blockIdx.x * blockDim.x + threadIdx.x;
    if (i < N_NODES) g_cnt[i] = 0;
}

__global__ void hist_k(const int* __restrict__ ei)
{
    int e = blockIdx.x * blockDim.x + threadIdx.x;
    if (e < N_EDGES) atomicAdd(&g_cnt[__ldg(ei + e)], 1);
}

#define SCAN_T 1024
#define SCAN_CHUNK ((N_NODES + SCAN_T - 1) / SCAN_T)   // 98
__global__ __launch_bounds__(SCAN_T)
void scan_k()
{
    __shared__ int s[SCAN_T];
    const int t = threadIdx.x;
    const int base = t * SCAN_CHUNK;
    int sum = 0;
    for (int i = 0; i < SCAN_CHUNK; i++) {
        int idx = base + i;
        if (idx < N_NODES) sum += g_cnt[idx];
    }
    s[t] = sum;
    __syncthreads();
    for (int off = 1; off < SCAN_T; off <<= 1) {
        int v = (t >= off) ? s[t - off] : 0;
        __syncthreads();
        s[t] += v;
        __syncthreads();
    }
    int run = (t == 0) ? 0 : s[t - 1];
    for (int i = 0; i < SCAN_CHUNK; i++) {
        int idx = base + i;
        if (idx < N_NODES) {
            g_row[idx] = run;
            g_cur[idx] = run;
            run += g_cnt[idx];
        }
    }
    if (t == 0) g_row[N_NODES] = s[SCAN_T - 1];
}

__global__ void fill_k(const int* __restrict__ ei, const float* __restrict__ mask)
{
    int e = blockIdx.x * blockDim.x + threadIdx.x;
    if (e >= N_EDGES) return;
    const int dst = __ldg(ei + e);
    const int src = __ldg(ei + N_EDGES + e);
    const float m = __ldg(mask + e);
    int pos = atomicAdd(&g_cur[dst], 1);
    g_edge[pos] = make_int2(src, __float_as_int(m));
}

// ================= fused gather: g_agg[n] = (1+eps)*h[n] + sum m*h[src] ======
// one warp per node, lane handles 4 features. Unroll-4 edge prefetch for MLP.
__global__ __launch_bounds__(256)
void gather_k(const float* __restrict__ h, const float* __restrict__ eps, int l)
{
    const int warp = (blockIdx.x * blockDim.x + threadIdx.x) >> 5;
    const int lane = threadIdx.x & 31;
    if (warp >= N_NODES) return;
    const float4* __restrict__ h4 = (const float4*)h;
    const float e1 = 1.0f + __ldg(eps + l);

    float4 v = __ldg(h4 + (size_t)warp * 32 + lane);
    float4 acc = make_float4(v.x * e1, v.y * e1, v.z * e1, v.w * e1);

    int e = g_row[warp];
    const int r1 = g_row[warp + 1];
    for (; e + 4 <= r1; e += 4) {
        // 4 broadcast edge loads (same L1 line), then 4 independent row loads
        int2 p0 = g_edge[e];
        int2 p1 = g_edge[e + 1];
        int2 p2 = g_edge[e + 2];
        int2 p3 = g_edge[e + 3];
        float4 v0 = __ldg(h4 + (size_t)p0.x * 32 + lane);
        float4 v1 = __ldg(h4 + (size_t)p1.x * 32 + lane);
        float4 v2 = __ldg(h4 + (size_t)p2.x * 32 + lane);
        float4 v3 = __ldg(h4 + (size_t)p3.x * 32 + lane);
        float m0 = __int_as_float(p0.y), m1 = __int_as_float(p1.y);
        float m2 = __int_as_float(p2.y), m3 = __int_as_float(p3.y);
        acc.x = fmaf(m0, v0.x, acc.x); acc.y = fmaf(m0, v0.y, acc.y);
        acc.z = fmaf(m0, v0.z, acc.z); acc.w = fmaf(m0, v0.w, acc.w);
        acc.x = fmaf(m1, v1.x, acc.x); acc.y = fmaf(m1, v1.y, acc.y);
        acc.z = fmaf(m1, v1.z, acc.z); acc.w = fmaf(m1, v1.w, acc.w);
        acc.x = fmaf(m2, v2.x, acc.x); acc.y = fmaf(m2, v2.y, acc.y);
        acc.z = fmaf(m2, v2.z, acc.z); acc.w = fmaf(m2, v2.w, acc.w);
        acc.x = fmaf(m3, v3.x, acc.x); acc.y = fmaf(m3, v3.y, acc.y);
        acc.z = fmaf(m3, v3.z, acc.z); acc.w = fmaf(m3, v3.w, acc.w);
    }
    for (; e < r1; e++) {
        int2 p0 = g_edge[e];
        float4 v0 = __ldg(h4 + (size_t)p0.x * 32 + lane);
        float m0 = __int_as_float(p0.y);
        acc.x = fmaf(m0, v0.x, acc.x); acc.y = fmaf(m0, v0.y, acc.y);
        acc.z = fmaf(m0, v0.z, acc.z); acc.w = fmaf(m0, v0.w, acc.w);
    }
    ((float4*)g_agg)[(size_t)warp * 32 + lane] = acc;
}

// ================= pooling =================
__global__ void zero_pool_k(float* __restrict__ pooled)
{
    int i = blockIdx.x * blockDim.x + threadIdx.x;
    if (i < N_GRAPHS * D) pooled[i] = 0.0f;
}

// one block per (128-node chunk, layer); run-accumulate, flush at graph change
#define POOL_CHUNK 128
#define N_CHUNKS ((N_NODES + POOL_CHUNK - 1) / POOL_CHUNK)   // 782
__global__ __launch_bounds__(128)
void pool_chunk_k(const float* __restrict__ embeds,
                  const int* __restrict__ batch,
                  float* __restrict__ pooled)
{
    const int chunk = blockIdx.x;
    const int l = blockIdx.y;
    const int j = threadIdx.x;     // feature 0..127
    const int n0 = chunk * POOL_CHUNK;
    const int n1 = min(n0 + POOL_CHUNK, N_NODES);
    const float* __restrict__ base = embeds + (size_t)l * EMB;

    float acc = 0.0f;
    int cur = __ldg(batch + n0);
    for (int n = n0; n < n1; n++) {
        int b = __ldg(batch + n);          // broadcast, uniform across block
        if (b != cur) {
            atomicAdd(&pooled[cur * D + j], acc);
            acc = 0.0f;
            cur = b;
        }
        acc += base[(size_t)n * D + j];
    }
    atomicAdd(&pooled[cur * D + j], acc);
}

// ================= head =================
__global__ void head_k(const float* __restrict__ pooled,
                       const float* __restrict__ W1, const float* __restrict__ b1,
                       const float* __restrict__ W2, const float* __restrict__ b2,
                       float* __restrict__ lin1, float* __restrict__ lin1d,
                       float* __restrict__ lin2, float* __restrict__ soft)
{
    const int g = blockIdx.x;
    const int j = threadIdx.x;
    __shared__ float ps[D];
    __shared__ float l1[D];
    __shared__ float lo[8];

    ps[j] = pooled[g * D + j];
    __syncthreads();

    float acc = __ldg(b1 + j);
    const float4* wr = (const float4*)(W1 + (size_t)j * D);
#pragma unroll 8
    for (int k4 = 0; k4 < 32; k4++) {
        float4 w = __ldg(wr + k4);
        acc = fmaf(ps[k4 * 4 + 0], w.x, acc);
        acc = fmaf(ps[k4 * 4 + 1], w.y, acc);
        acc = fmaf(ps[k4 * 4 + 2], w.z, acc);
        acc = fmaf(ps[k4 * 4 + 3], w.w, acc);
    }
    acc = fmaxf(acc, 0.0f);
    lin1[g * D + j] = acc;
    lin1d[g * D + j] = acc;
    l1[j] = acc;
    __syncthreads();

    if (j < 8) {
        float a2 = __ldg(b2 + j);
        const float4* w2r = (const float4*)(W2 + (size_t)j * D);
#pragma unroll 8
        for (int k4 = 0; k4 < 32; k4++) {
            float4 w = __ldg(w2r + k4);
            a2 = fmaf(l1[k4 * 4 + 0], w.x, a2);
            a2 = fmaf(l1[k4 * 4 + 1], w.y, a2);
            a2 = fmaf(l1[k4 * 4 + 2], w.z, a2);
            a2 = fmaf(l1[k4 * 4 + 3], w.w, a2);
        }
        lin2[g * 8 + j] = a2;
        lo[j] = a2;
    }
    __syncthreads();
    if (j < 8) {
        float m = lo[0];
#pragma unroll
        for (int t = 1; t < 8; t++) m = fmaxf(m, lo[t]);
        float s = 0.0f;
#pragma unroll
        for (int t = 0; t < 8; t++) s += expf(lo[t] - m);
        soft[g * 8 + j] = expf(lo[j] - m) / s;
    }
}

// ================= launch =================
extern "C" void kernel_launch(void* const* d_in, const int* in_sizes, int n_in,
                              void* d_out, int out_size)
{
    const float* x       = (const float*)d_in[0];
    const int*   ei      = (const int*)  d_in[1];
    const float* emask   = (const float*)d_in[2];
    const int*   batch   = (const int*)  d_in[3];
    const float* eps     = (const float*)d_in[4];
    const float* W_first = (const float*)d_in[5];
    const float* b_first = (const float*)d_in[6];
    const float* gin_W   = (const float*)d_in[7];
    const float* gin_b   = (const float*)d_in[8];
    const float* W1      = (const float*)d_in[9];
    const float* b1      = (const float*)d_in[10];
    const float* W2      = (const float*)d_in[11];
    const float* b2      = (const float*)d_in[12];
    float* out = (float*)d_out;

    const dim3 gB((N_NODES + 127) / 128);
    const int eB = (N_EDGES + 255) / 256;

    // ---- CSR build (once per launch; reused by 4 gathers) ----
    zero_cnt_k<<<(N_NODES + 255) / 256, 256>>>();
    hist_k<<<eB, 256>>>(ei);
    scan_k<<<1, SCAN_T>>>();
    fill_k<<<eB, 256>>>(ei, emask);

    // embeds[0] = x @ W_first^T + b_first (no relu)
    gemm128<<<gB, 256>>>(x, BUF_EXT, W_first, b_first, out, BUF_EXT, N_NODES, 0);

    for (int l = 0; l < 4; l++) {
        const float* h = out + (size_t)l * EMB;
        gather_k<<<(N_NODES * 32 + 255) / 256, 256>>>(h, eps, l);
        gemm128<<<gB, 256>>>(nullptr, BUF_AGG, gin_W + (size_t)(2 * l) * D * D,
                             gin_b + (2 * l) * D, nullptr, BUF_TMP, N_NODES, 1);
        gemm128<<<gB, 256>>>(nullptr, BUF_TMP, gin_W + (size_t)(2 * l + 1) * D * D,
                             gin_b + (2 * l + 1) * D, out + (size_t)(l + 1) * EMB,
                             BUF_EXT, N_NODES, 1);
    }

    zero_pool_k<<<(N_GRAPHS * D + 255) / 256, 256>>>(out + OFF_POOLED);
    {
        dim3 pg(N_CHUNKS, 5);
        pool_chunk_k<<<pg, 128>>>(out, batch, out + OFF_POOLED);
    }
    head_k<<<N_GRAPHS, 128>>>(out + OFF_POOLED, W1, b1, W2, b2,
                              out + OFF_LIN1, out + OFF_LIN1D,
                              out + OFF_LIN2, out + OFF_SOFT);
}

// round 8
// speedup vs baseline: 2.1881x; 1.0585x over previous
#include <cuda_runtime.h>
#include <math.h>
#include <stdint.h>

#define N_NODES 100000
#define N_EDGES 1600000
#define N_GRAPHS 256
#define D 128
#define EMB (N_NODES * D)

// ---------------- scratch (device globals: no allocation) ----------------
__device__ float g_agg[EMB];
__device__ float g_tmp[EMB];
__device__ int2  g_edge[N_EDGES];     // packed {src, mask bits} sorted by dst
__device__ int   g_row[N_NODES + 1];  // CSR row starts
__device__ int   g_cur[N_NODES];      // fill cursors
__device__ int   g_cnt[N_NODES];      // histogram

// ---------------- output layout (flattened tuple) ----------------
#define OFF_POOLED 64000000
#define OFF_LIN1   64032768
#define OFF_LIN1D  64065536
#define OFF_LIN2   64098304
#define OFF_SOFT   64100352

#define BUF_EXT 0
#define BUF_AGG 1
#define BUF_TMP 2

// ---- packed f32x2 helpers (sm_103a) ----
#define FMA2(d, a, b)  asm("fma.rn.f32x2 %0, %1, %2, %0;" : "+l"(d) : "l"(a), "l"(b))
#define BCAST2(d, s)   asm("mov.b64 %0, {%1, %1};" : "=l"(d) : "f"(s))
#define PACK2(d, lo, hi) asm("mov.b64 %0, {%1, %2};" : "=l"(d) : "f"(lo), "f"(hi))
#define UNPACK2(lo, hi, s) asm("mov.b64 {%0, %1}, %2;" : "=f"(lo), "=f"(hi) : "l"(s))

// ================= GEMM: C[i][j] = sum_k A[i][k] * W[j][k] + b[j] =================
// Inner product in packed f32x2: acc pairs along columns, A broadcast, W pair-packed.
__global__ __launch_bounds__(256, 2)
void gemm128(const float* __restrict__ Aext, int aSel,
             const float* __restrict__ W,
             const float* __restrict__ bias,
             float* __restrict__ Cext, int cSel,
             int N, int doRelu)
{
    const float* A = (aSel == BUF_AGG) ? g_agg : (aSel == BUF_TMP) ? g_tmp : Aext;
    float*       C = (cSel == BUF_AGG) ? g_agg : (cSel == BUF_TMP) ? g_tmp : Cext;

    __shared__ __align__(16) float As[2][16][132];
    __shared__ __align__(16) float Ws[2][16][132];

    const int tid  = threadIdx.x;
    const int row0 = blockIdx.x * 128;
    const int q    = tid & 3;
    const int ld   = tid >> 2;
    const int ci   = tid & 15;
    const int ri   = tid >> 4;

    // acc2[r][c] packs output cols (2c, 2c+1) for row r
    uint64_t acc2[8][4];
#pragma unroll
    for (int r = 0; r < 8; r++)
#pragma unroll
        for (int c = 0; c < 4; c++) acc2[r][c] = 0ull;

    float4 ra0, ra1, rw0, rw1;

    auto ldg_chunk = [&](int kc) {
        const int k = kc * 16 + q * 4;
        const int r0 = row0 + ld, r1 = row0 + ld + 64;
        ra0 = (r0 < N) ? *(const float4*)(A + (size_t)r0 * D + k) : make_float4(0.f, 0.f, 0.f, 0.f);
        ra1 = (r1 < N) ? *(const float4*)(A + (size_t)r1 * D + k) : make_float4(0.f, 0.f, 0.f, 0.f);
        rw0 = *(const float4*)(W + (size_t)ld * D + k);
        rw1 = *(const float4*)(W + (size_t)(ld + 64) * D + k);
    };
    auto sts_chunk = [&](int buf) {
        const int kk = q * 4;
        As[buf][kk + 0][ld] = ra0.x; As[buf][kk + 1][ld] = ra0.y;
        As[buf][kk + 2][ld] = ra0.z; As[buf][kk + 3][ld] = ra0.w;
        As[buf][kk + 0][ld + 64] = ra1.x; As[buf][kk + 1][ld + 64] = ra1.y;
        As[buf][kk + 2][ld + 64] = ra1.z; As[buf][kk + 3][ld + 64] = ra1.w;
        Ws[buf][kk + 0][ld] = rw0.x; Ws[buf][kk + 1][ld] = rw0.y;
        Ws[buf][kk + 2][ld] = rw0.z; Ws[buf][kk + 3][ld] = rw0.w;
        Ws[buf][kk + 0][ld + 64] = rw1.x; Ws[buf][kk + 1][ld + 64] = rw1.y;
        Ws[buf][kk + 2][ld + 64] = rw1.z; Ws[buf][kk + 3][ld + 64] = rw1.w;
    };

    ldg_chunk(0);
    sts_chunk(0);
    __syncthreads();

    for (int kc = 0; kc < 8; kc++) {
        const int buf = kc & 1;
        if (kc < 7) ldg_chunk(kc + 1);
#pragma unroll
        for (int kk = 0; kk < 16; kk++) {
            float4 a0 = *(const float4*)&As[buf][kk][ri * 4];
            float4 a1 = *(const float4*)&As[buf][kk][64 + ri * 4];
            float4 w0 = *(const float4*)&Ws[buf][kk][ci * 4];
            float4 w1 = *(const float4*)&Ws[buf][kk][64 + ci * 4];

            uint64_t wP[4];
            PACK2(wP[0], w0.x, w0.y); PACK2(wP[1], w0.z, w0.w);
            PACK2(wP[2], w1.x, w1.y); PACK2(wP[3], w1.z, w1.w);

            float a[8] = {a0.x, a0.y, a0.z, a0.w, a1.x, a1.y, a1.z, a1.w};
#pragma unroll
            for (int r = 0; r < 8; r++) {
                uint64_t aP;
                BCAST2(aP, a[r]);
#pragma unroll
                for (int c = 0; c < 4; c++)
                    FMA2(acc2[r][c], aP, wP[c]);
            }
        }
        if (kc < 7) {
            sts_chunk(buf ^ 1);
            __syncthreads();
        }
    }

    float bv[8];
#pragma unroll
    for (int hc = 0; hc < 2; hc++)
#pragma unroll
        for (int c = 0; c < 4; c++)
            bv[hc * 4 + c] = __ldg(bias + hc * 64 + ci * 4 + c);

#pragma unroll
    for (int hr = 0; hr < 2; hr++) {
#pragma unroll
        for (int r = 0; r < 4; r++) {
            const int row = row0 + hr * 64 + ri * 4 + r;
            if (row < N) {
#pragma unroll
                for (int hc = 0; hc < 2; hc++) {
                    const int col = hc * 64 + ci * 4;
                    float e0, e1, e2, e3;
                    UNPACK2(e0, e1, acc2[hr * 4 + r][hc * 2 + 0]);
                    UNPACK2(e2, e3, acc2[hr * 4 + r][hc * 2 + 1]);
                    float4 o;
                    o.x = e0 + bv[hc * 4 + 0];
                    o.y = e1 + bv[hc * 4 + 1];
                    o.z = e2 + bv[hc * 4 + 2];
                    o.w = e3 + bv[hc * 4 + 3];
                    if (doRelu) {
                        o.x = fmaxf(o.x, 0.f); o.y = fmaxf(o.y, 0.f);
                        o.z = fmaxf(o.z, 0.f); o.w = fmaxf(o.w, 0.f);
                    }
                    *(float4*)(C + (size_t)row * D + col) = o;
                }
            }
        }
    }
}

// ================= CSR build =================
__global__ void zero_cnt_k()
{
    int i = blockIdx.x * blockDim.x + threadIdx.x;
    if (i < N_NODES) g_cnt[i] = 0;
}

__global__ void hist_k(const int* __restrict__ ei)
{
    int e = blockIdx.x * blockDim.x + threadIdx.x;
    if (e < N_EDGES) atomicAdd(&g_cnt[__ldg(ei + e)], 1);
}

#define SCAN_T 1024
#define SCAN_CHUNK ((N_NODES + SCAN_T - 1) / SCAN_T)   // 98
__global__ __launch_bounds__(SCAN_T)
void scan_k()
{
    __shared__ int s[SCAN_T];
    const int t = threadIdx.x;
    const int base = t * SCAN_CHUNK;
    int sum = 0;
    for (int i = 0; i < SCAN_CHUNK; i++) {
        int idx = base + i;
        if (idx < N_NODES) sum += g_cnt[idx];
    }
    s[t] = sum;
    __syncthreads();
    for (int off = 1; off < SCAN_T; off <<= 1) {
        int v = (t >= off) ? s[t - off] : 0;
        __syncthreads();
        s[t] += v;
        __syncthreads();
    }
    int run = (t == 0) ? 0 : s[t - 1];
    for (int i = 0; i < SCAN_CHUNK; i++) {
        int idx = base + i;
        if (idx < N_NODES) {
            g_row[idx] = run;
            g_cur[idx] = run;
            run += g_cnt[idx];
        }
    }
    if (t == 0) g_row[N_NODES] = s[SCAN_T - 1];
}

__global__ void fill_k(const int* __restrict__ ei, const float* __restrict__ mask)
{
    int e = blockIdx.x * blockDim.x + threadIdx.x;
    if (e >= N_EDGES) return;
    const int dst = __ldg(ei + e);
    const int src = __ldg(ei + N_EDGES + e);
    const float m = __ldg(mask + e);
    int pos = atomicAdd(&g_cur[dst], 1);
    g_edge[pos] = make_int2(src, __float_as_int(m));
}

// ================= fused gather: g_agg[n] = (1+eps)*h[n] + sum m*h[src] ======
__global__ __launch_bounds__(256)
void gather_k(const float* __restrict__ h, const float* __restrict__ eps, int l)
{
    const int warp = (blockIdx.x * blockDim.x + threadIdx.x) >> 5;
    const int lane = threadIdx.x & 31;
    if (warp >= N_NODES) return;
    const float4* __restrict__ h4 = (const float4*)h;
    const float e1 = 1.0f + __ldg(eps + l);

    float4 v = __ldg(h4 + (size_t)warp * 32 + lane);
    float4 acc = make_float4(v.x * e1, v.y * e1, v.z * e1, v.w * e1);

    int e = g_row[warp];
    const int r1 = g_row[warp + 1];
    for (; e + 4 <= r1; e += 4) {
        int2 p0 = g_edge[e];
        int2 p1 = g_edge[e + 1];
        int2 p2 = g_edge[e + 2];
        int2 p3 = g_edge[e + 3];
        float4 v0 = __ldg(h4 + (size_t)p0.x * 32 + lane);
        float4 v1 = __ldg(h4 + (size_t)p1.x * 32 + lane);
        float4 v2 = __ldg(h4 + (size_t)p2.x * 32 + lane);
        float4 v3 = __ldg(h4 + (size_t)p3.x * 32 + lane);
        float m0 = __int_as_float(p0.y), m1 = __int_as_float(p1.y);
        float m2 = __int_as_float(p2.y), m3 = __int_as_float(p3.y);
        acc.x = fmaf(m0, v0.x, acc.x); acc.y = fmaf(m0, v0.y, acc.y);
        acc.z = fmaf(m0, v0.z, acc.z); acc.w = fmaf(m0, v0.w, acc.w);
        acc.x = fmaf(m1, v1.x, acc.x); acc.y = fmaf(m1, v1.y, acc.y);
        acc.z = fmaf(m1, v1.z, acc.z); acc.w = fmaf(m1, v1.w, acc.w);
        acc.x = fmaf(m2, v2.x, acc.x); acc.y = fmaf(m2, v2.y, acc.y);
        acc.z = fmaf(m2, v2.z, acc.z); acc.w = fmaf(m2, v2.w, acc.w);
        acc.x = fmaf(m3, v3.x, acc.x); acc.y = fmaf(m3, v3.y, acc.y);
        acc.z = fmaf(m3, v3.z, acc.z); acc.w = fmaf(m3, v3.w, acc.w);
    }
    for (; e < r1; e++) {
        int2 p0 = g_edge[e];
        float4 v0 = __ldg(h4 + (size_t)p0.x * 32 + lane);
        float m0 = __int_as_float(p0.y);
        acc.x = fmaf(m0, v0.x, acc.x); acc.y = fmaf(m0, v0.y, acc.y);
        acc.z = fmaf(m0, v0.z, acc.z); acc.w = fmaf(m0, v0.w, acc.w);
    }
    ((float4*)g_agg)[(size_t)warp * 32 + lane] = acc;
}

// ================= pooling =================
__global__ void zero_pool_k(float* __restrict__ pooled)
{
    int i = blockIdx.x * blockDim.x + threadIdx.x;
    if (i < N_GRAPHS * D) pooled[i] = 0.0f;
}

#define POOL_CHUNK 128
#define N_CHUNKS ((N_NODES + POOL_CHUNK - 1) / POOL_CHUNK)   // 782
__global__ __launch_bounds__(128)
void pool_chunk_k(const float* __restrict__ embeds,
                  const int* __restrict__ batch,
                  float* __restrict__ pooled)
{
    const int chunk = blockIdx.x;
    const int l = blockIdx.y;
    const int j = threadIdx.x;
    const int n0 = chunk * POOL_CHUNK;
    const int n1 = min(n0 + POOL_CHUNK, N_NODES);
    const float* __restrict__ base = embeds + (size_t)l * EMB;

    float acc = 0.0f;
    int cur = __ldg(batch + n0);
    for (int n = n0; n < n1; n++) {
        int b = __ldg(batch + n);
        if (b != cur) {
            atomicAdd(&pooled[cur * D + j], acc);
            acc = 0.0f;
            cur = b;
        }
        acc += base[(size_t)n * D + j];
    }
    atomicAdd(&pooled[cur * D + j], acc);
}

// ================= head =================
__global__ void head_k(const float* __restrict__ pooled,
                       const float* __restrict__ W1, const float* __restrict__ b1,
                       const float* __restrict__ W2, const float* __restrict__ b2,
                       float* __restrict__ lin1, float* __restrict__ lin1d,
                       float* __restrict__ lin2, float* __restrict__ soft)
{
    const int g = blockIdx.x;
    const int j = threadIdx.x;
    __shared__ float ps[D];
    __shared__ float l1[D];
    __shared__ float lo[8];

    ps[j] = pooled[g * D + j];
    __syncthreads();

    float acc = __ldg(b1 + j);
    const float4* wr = (const float4*)(W1 + (size_t)j * D);
#pragma unroll 8
    for (int k4 = 0; k4 < 32; k4++) {
        float4 w = __ldg(wr + k4);
        acc = fmaf(ps[k4 * 4 + 0], w.x, acc);
        acc = fmaf(ps[k4 * 4 + 1], w.y, acc);
        acc = fmaf(ps[k4 * 4 + 2], w.z, acc);
        acc = fmaf(ps[k4 * 4 + 3], w.w, acc);
    }
    acc = fmaxf(acc, 0.0f);
    lin1[g * D + j] = acc;
    lin1d[g * D + j] = acc;
    l1[j] = acc;
    __syncthreads();

    if (j < 8) {
        float a2 = __ldg(b2 + j);
        const float4* w2r = (const float4*)(W2 + (size_t)j * D);
#pragma unroll 8
        for (int k4 = 0; k4 < 32; k4++) {
            float4 w = __ldg(w2r + k4);
            a2 = fmaf(l1[k4 * 4 + 0], w.x, a2);
            a2 = fmaf(l1[k4 * 4 + 1], w.y, a2);
            a2 = fmaf(l1[k4 * 4 + 2], w.z, a2);
            a2 = fmaf(l1[k4 * 4 + 3], w.w, a2);
        }
        lin2[g * 8 + j] = a2;
        lo[j] = a2;
    }
    __syncthreads();
    if (j < 8) {
        float m = lo[0];
#pragma unroll
        for (int t = 1; t < 8; t++) m = fmaxf(m, lo[t]);
        float s = 0.0f;
#pragma unroll
        for (int t = 0; t < 8; t++) s += expf(lo[t] - m);
        soft[g * 8 + j] = expf(lo[j] - m) / s;
    }
}

// ================= launch =================
extern "C" void kernel_launch(void* const* d_in, const int* in_sizes, int n_in,
                              void* d_out, int out_size)
{
    const float* x       = (const float*)d_in[0];
    const int*   ei      = (const int*)  d_in[1];
    const float* emask   = (const float*)d_in[2];
    const int*   batch   = (const int*)  d_in[3];
    const float* eps     = (const float*)d_in[4];
    const float* W_first = (const float*)d_in[5];
    const float* b_first = (const float*)d_in[6];
    const float* gin_W   = (const float*)d_in[7];
    const float* gin_b   = (const float*)d_in[8];
    const float* W1      = (const float*)d_in[9];
    const float* b1      = (const float*)d_in[10];
    const float* W2      = (const float*)d_in[11];
    const float* b2      = (const float*)d_in[12];
    float* out = (float*)d_out;

    const dim3 gB((N_NODES + 127) / 128);
    const int eB = (N_EDGES + 255) / 256;

    // ---- CSR build (once per launch; reused by 4 gathers) ----
    zero_cnt_k<<<(N_NODES + 255) / 256, 256>>>();
    hist_k<<<eB, 256>>>(ei);
    scan_k<<<1, SCAN_T>>>();
    fill_k<<<eB, 256>>>(ei, emask);

    // embeds[0] = x @ W_first^T + b_first (no relu)
    gemm128<<<gB, 256>>>(x, BUF_EXT, W_first, b_first, out, BUF_EXT, N_NODES, 0);

    for (int l = 0; l < 4; l++) {
        const float* h = out + (size_t)l * EMB;
        gather_k<<<(N_NODES * 32 + 255) / 256, 256>>>(h, eps, l);
        gemm128<<<gB, 256>>>(nullptr, BUF_AGG, gin_W + (size_t)(2 * l) * D * D,
                             gin_b + (2 * l) * D, nullptr, BUF_TMP, N_NODES, 1);
        gemm128<<<gB, 256>>>(nullptr, BUF_TMP, gin_W + (size_t)(2 * l + 1) * D * D,
                             gin_b + (2 * l + 1) * D, out + (size_t)(l + 1) * EMB,
                             BUF_EXT, N_NODES, 1);
    }

    zero_pool_k<<<(N_GRAPHS * D + 255) / 256, 256>>>(out + OFF_POOLED);
    {
        dim3 pg(N_CHUNKS, 5);
        pool_chunk_k<<<pg, 128>>>(out, batch, out + OFF_POOLED);
    }
    head_k<<<N_GRAPHS, 128>>>(out + OFF_POOLED, W1, b1, W2, b2,
                              out + OFF_LIN1, out + OFF_LIN1D,
                              out + OFF_LIN2, out + OFF_SOFT);
}